// round 9
// baseline (speedup 1.0000x reference)
#include <cuda_runtime.h>
#include <cstdint>

// Problem constants
#define Bq     8
#define NIN    512
#define NOUT   1024
#define Cc     16
#define OUTC   32
#define KW     5

// Conv tiling
#define CNTILE 32
#define CTHREADS 128

// Gauss-MMA tiling
#define MTILE  64                 // m per block
#define MT     (NOUT / MTILE)     // 16
#define GTHREADS 1024             // 32 warps: 4 m-subtiles x 8 k-eighths
#define KQ     8                  // k-chunks
#define KSTEPS ((NIN / KQ) / 8)   // 8 ksteps per warp

#define LOG2E 1.4426950408889634f

// conv output, stored PRE-SWIZZLED per batch in the gauss fragment layout:
// off(n,c) = (n>>2)*64 + (c>>3)*32 + (n&3)*8 + (c&7)
__device__ float g_rt[Bq * NIN * Cc];

__device__ __forceinline__ float ex2a(float x) {
    float r; asm("ex2.approx.f32 %0, %1;" : "=f"(r) : "f"(x)); return r;
}
__device__ __forceinline__ unsigned f2tf32(float x) {
    unsigned r; asm("cvt.rna.tf32.f32 %0, %1;" : "=r"(r) : "f"(x)); return r;
}
__device__ __forceinline__ void mma_tf32(float d[4], const unsigned a[4],
                                         unsigned b0, unsigned b1) {
    asm volatile(
        "mma.sync.aligned.m16n8k8.row.col.f32.tf32.tf32.f32 "
        "{%0,%1,%2,%3}, {%4,%5,%6,%7}, {%8,%9}, {%0,%1,%2,%3};"
        : "+f"(d[0]), "+f"(d[1]), "+f"(d[2]), "+f"(d[3])
        : "r"(a[0]), "r"(a[1]), "r"(a[2]), "r"(a[3]), "r"(b0), "r"(b1));
}

// ---------------------------------------------------------------------------
// Kernel 1: Conv1d (NCH, OIH, SAME pad=2) + bias -> g_rt (tf32-rounded,
// pre-swizzled). grid (16, 8) = 128 blocks, block 128.
// ---------------------------------------------------------------------------
__global__ void conv_kernel(const float* __restrict__ r,
                            const float* __restrict__ w,
                            const float* __restrict__ bias) {
    __shared__ float sr[Cc][CNTILE + 4];
    __shared__ float sws[Cc * KW * Cc];   // [ci][k][c_out]
    __shared__ float sb[Cc];

    const int b  = blockIdx.y;
    const int n0 = blockIdx.x * CNTILE;
    const int t  = threadIdx.x;

    for (int i = t; i < Cc * (CNTILE + 4); i += CTHREADS) {
        int ci = i / (CNTILE + 4);
        int j  = i % (CNTILE + 4);
        int n  = n0 + j - 2;
        sr[ci][j] = (n >= 0 && n < NIN) ? r[((size_t)b * Cc + ci) * NIN + n] : 0.0f;
    }
    for (int i = t; i < Cc * Cc * KW; i += CTHREADS) {
        int c  = i / (Cc * KW);
        int rm = i % (Cc * KW);
        int ci = rm / KW;
        int k  = rm % KW;
        sws[(ci * KW + k) * Cc + c] = w[i];
    }
    if (t < Cc) sb[t] = bias[t];
    __syncthreads();

    const int nl = t & (CNTILE - 1);
    const int cg = t >> 5;            // 0..3, channels cg*4..cg*4+3
    const int n  = n0 + nl;

    float4 a;
    a.x = sb[cg * 4 + 0]; a.y = sb[cg * 4 + 1];
    a.z = sb[cg * 4 + 2]; a.w = sb[cg * 4 + 3];

    #pragma unroll
    for (int k = 0; k < KW; k++) {
        #pragma unroll
        for (int ci = 0; ci < Cc; ci++) {
            float v = sr[ci][nl + k];
            float4 wv = *reinterpret_cast<const float4*>(&sws[(ci * KW + k) * Cc + cg * 4]);
            a.x += v * wv.x; a.y += v * wv.y; a.z += v * wv.z; a.w += v * wv.w;
        }
    }

    a.x = __uint_as_float(f2tf32(a.x));
    a.y = __uint_as_float(f2tf32(a.y));
    a.z = __uint_as_float(f2tf32(a.z));
    a.w = __uint_as_float(f2tf32(a.w));

    const int c4  = cg * 4;
    const int off = (n >> 2) * 64 + (c4 >> 3) * 32 + (n & 3) * 8 + (c4 & 7);
    *reinterpret_cast<float4*>(g_rt + (size_t)b * NIN * Cc + off) = a;
}

// ---------------------------------------------------------------------------
// Kernel 2: Gaussian transform as tf32 MMA + k-reduce + linear C->OUT_C.
// grid (MT, B) = (16, 8) = 128 blocks, block 1024 (32 warps, 8/SMSP).
// Warp w: msub = w&3 (16 m rows), kq = w>>2 (64 n). Per kstep (8 n):
// thread computes its 4 A-fragment exps in registers (ex2 bits fed straight
// to the tf32 MMA — HW truncation, no CVT in chain); B fragments are
// conflict-free LDS.32 from the pre-swizzled rt copy.
// ---------------------------------------------------------------------------
__global__ void __launch_bounds__(GTHREADS, 1)
gauss_mma_kernel(const float* __restrict__ xc,
                 const float* __restrict__ xt,
                 const float* __restrict__ sigma,
                 const float* __restrict__ lw,
                 const float* __restrict__ lb,
                 float* __restrict__ out) {
    __shared__ __align__(16) float sB[NIN * Cc];          // 32 KB (pre-swizzled)
    __shared__ float shx[NIN];                            // 2 KB
    __shared__ __align__(16) float zred[KQ][MTILE][Cc];   // 32 KB partials
    __shared__ float shlw[OUTC * Cc];                     // 2 KB
    __shared__ float sh_nh[Cc];
    __shared__ int   sh_alleq;

    const int b  = blockIdx.y;
    const int mt = blockIdx.x;
    const int t  = threadIdx.x;
    const int l  = t & 31;
    const int w  = t >> 5;
    const int msub = w & 3;
    const int kq   = w >> 2;

    if (t < Cc) {
        float sg = sigma[t];
        sh_nh[t] = -0.5f * expf(-2.0f * sg) * LOG2E;
    }
    if (t == 0) {
        float s0 = sigma[0];
        int eq = 1;
        #pragma unroll
        for (int c = 1; c < Cc; c++) eq &= (sigma[c] == s0);
        sh_alleq = eq;
    }
    for (int i = t; i < NIN; i += GTHREADS) shx[i] = xc[(size_t)b * NIN + i];
    // straight coalesced copy (already swizzled)
    {
        const float4* src = reinterpret_cast<const float4*>(g_rt + (size_t)b * NIN * Cc);
        float4* dst = reinterpret_cast<float4*>(sB);
        #pragma unroll
        for (int j = t; j < NIN * Cc / 4; j += GTHREADS) dst[j] = src[j];
    }
    for (int i = t; i < OUTC * Cc; i += GTHREADS) shlw[i] = lw[i];
    __syncthreads();

    if (sh_alleq) {
        // ---- tf32 MMA fast path ----
        const float nh = sh_nh[0];
        const int mrow = mt * MTILE + msub * 16 + (l >> 2);
        const float xm0 = __ldg(xt + (size_t)b * NOUT + mrow);
        const float xm1 = __ldg(xt + (size_t)b * NOUT + mrow + 8);

        float D0[4] = {0.f, 0.f, 0.f, 0.f};
        float D1[4] = {0.f, 0.f, 0.f, 0.f};
        const int lof = (l & 3) * 8 + (l >> 2);
        const int kb  = kq * (NIN / KQ);

        #pragma unroll
        for (int ks = 0; ks < KSTEPS; ks++) {
            const int k0 = kb + ks * 8;
            float xna = shx[k0 + (l & 3)];
            float xnb = shx[k0 + 4 + (l & 3)];
            unsigned A[4];
            float d;
            // ex2 bits used directly as tf32 (HW truncates) — no CVT in chain
            d = xm0 - xna; A[0] = __float_as_uint(ex2a(d * d * nh));
            d = xm1 - xna; A[1] = __float_as_uint(ex2a(d * d * nh));
            d = xm0 - xnb; A[2] = __float_as_uint(ex2a(d * d * nh));
            d = xm1 - xnb; A[3] = __float_as_uint(ex2a(d * d * nh));
            const int kbase = (k0 >> 2) * 64 + lof;
            unsigned b00 = __float_as_uint(sB[kbase]);
            unsigned b01 = __float_as_uint(sB[kbase + 64]);
            unsigned b10 = __float_as_uint(sB[kbase + 32]);
            unsigned b11 = __float_as_uint(sB[kbase + 96]);
            mma_tf32(D0, A, b00, b01);
            mma_tf32(D1, A, b10, b11);
        }

        const int ml = msub * 16 + (l >> 2);
        const int c0 = (l & 3) * 2;
        *reinterpret_cast<float2*>(&zred[kq][ml][c0])         = make_float2(D0[0], D0[1]);
        *reinterpret_cast<float2*>(&zred[kq][ml + 8][c0])     = make_float2(D0[2], D0[3]);
        *reinterpret_cast<float2*>(&zred[kq][ml][c0 + 8])     = make_float2(D1[0], D1[1]);
        *reinterpret_cast<float2*>(&zred[kq][ml + 8][c0 + 8]) = make_float2(D1[2], D1[3]);
    } else {
        // ---- generic per-channel sigma fallback ----
        float nhc[8];
        const int chalf = l & 1;
        #pragma unroll
        for (int j = 0; j < 8; j++) nhc[j] = sh_nh[chalf * 8 + j];
        const int mloc = msub * 16 + (l >> 1);
        const float xm = __ldg(xt + (size_t)b * NOUT + mt * MTILE + mloc);
        float acc[8];
        #pragma unroll
        for (int j = 0; j < 8; j++) acc[j] = 0.0f;
        const int nbeg = kq * (NIN / KQ);
        for (int n = nbeg; n < nbeg + NIN / KQ; n++) {
            float dx = xm - shx[n];
            float d  = dx * dx;
            const int base = (n >> 2) * 64 + chalf * 32 + (n & 3) * 8;
            float4 ra = *reinterpret_cast<const float4*>(&sB[base]);
            float4 rb = *reinterpret_cast<const float4*>(&sB[base + 4]);
            acc[0] += ex2a(d * nhc[0]) * ra.x;
            acc[1] += ex2a(d * nhc[1]) * ra.y;
            acc[2] += ex2a(d * nhc[2]) * ra.z;
            acc[3] += ex2a(d * nhc[3]) * ra.w;
            acc[4] += ex2a(d * nhc[4]) * rb.x;
            acc[5] += ex2a(d * nhc[5]) * rb.y;
            acc[6] += ex2a(d * nhc[6]) * rb.z;
            acc[7] += ex2a(d * nhc[7]) * rb.w;
        }
        float* zp = &zred[kq][mloc][chalf * 8];
        *reinterpret_cast<float4*>(zp)     = make_float4(acc[0], acc[1], acc[2], acc[3]);
        *reinterpret_cast<float4*>(zp + 4) = make_float4(acc[4], acc[5], acc[6], acc[7]);
    }
    __syncthreads();

    // linear C -> OUT_C + bias: thread t -> (ml = t>>4, 2 outputs at og=(t&15)*2)
    {
        const int ml = t >> 4;            // 0..63
        const int og = (t & 15) * 2;      // 0..30
        float z[Cc];
        #pragma unroll
        for (int c = 0; c < Cc; c += 4) {
            float4 s0 = *reinterpret_cast<const float4*>(&zred[0][ml][c]);
            #pragma unroll
            for (int q = 1; q < KQ; q++) {
                float4 p = *reinterpret_cast<const float4*>(&zred[q][ml][c]);
                s0.x += p.x; s0.y += p.y; s0.z += p.z; s0.w += p.w;
            }
            z[c] = s0.x; z[c + 1] = s0.y; z[c + 2] = s0.z; z[c + 3] = s0.w;
        }
        float o0 = __ldg(lb + og);
        float o1 = __ldg(lb + og + 1);
        #pragma unroll
        for (int c = 0; c < Cc; c++) {
            float zc = z[c];
            o0 += zc * shlw[(og + 0) * Cc + c];
            o1 += zc * shlw[(og + 1) * Cc + c];
        }
        *reinterpret_cast<float2*>(
            out + (((size_t)b * NOUT) + mt * MTILE + ml) * OUTC + og) =
            make_float2(o0, o1);
    }
}

// ---------------------------------------------------------------------------
// Launch. Inputs (metadata order):
// 0 r (8,16,512) | 1 x_context (8,512,1) | 2 y_context (unused) |
// 3 x_target (8,1024,1) | 4 conv_w (16,16,5) | 5 conv_b (16) |
// 6 sigma (16) | 7 lin_w (32,16) | 8 lin_b (32)  -> out (8,1024,32) f32
// ---------------------------------------------------------------------------
extern "C" void kernel_launch(void* const* d_in, const int* in_sizes, int n_in,
                              void* d_out, int out_size) {
    const float* r      = (const float*)d_in[0];
    const float* xc     = (const float*)d_in[1];
    const float* xt     = (const float*)d_in[3];
    const float* conv_w = (const float*)d_in[4];
    const float* conv_b = (const float*)d_in[5];
    const float* sigma  = (const float*)d_in[6];
    const float* lin_w  = (const float*)d_in[7];
    const float* lin_b  = (const float*)d_in[8];
    float* out = (float*)d_out;

    conv_kernel<<<dim3(NIN / CNTILE, Bq), CTHREADS>>>(r, conv_w, conv_b);
    gauss_mma_kernel<<<dim3(MT, Bq), GTHREADS>>>(xc, xt, sigma, lin_w, lin_b, out);
}

// round 10
// speedup vs baseline: 1.0527x; 1.0527x over previous
#include <cuda_runtime.h>
#include <cstdint>

// Problem constants
#define Bq     8
#define NIN    512
#define NOUT   1024
#define Cc     16
#define OUTC   32
#define KW     5

// Conv tiling
#define CNTILE 32
#define CTHREADS 128

// Gauss-MMA tiling
#define MTILE  64                 // m per block
#define MT     (NOUT / MTILE)     // 16
#define GTHREADS 1024             // 32 warps: 4 m-subtiles x 8 k-eighths
#define KQ     8
#define KSTEPS 8                  // (NIN/KQ)/8

#define LOG2E 1.4426950408889634f

// conv output, stored in PER-THREAD FRAGMENT ORDER for the gauss MMA:
// off(n,c) = (n>>6)*1024 + ((n&63)>>3)*128 + ((c&7)*4+(n&3))*4
//            + ((n>>2)&1) + 2*(c>>3)
__device__ float g_rt[Bq * NIN * Cc];

__device__ __forceinline__ float ex2a(float x) {
    float r; asm("ex2.approx.f32 %0, %1;" : "=f"(r) : "f"(x)); return r;
}
__device__ __forceinline__ unsigned f2tf32(float x) {
    unsigned r; asm("cvt.rna.tf32.f32 %0, %1;" : "=r"(r) : "f"(x)); return r;
}
__device__ __forceinline__ void mma_tf32(float d[4], const unsigned a[4],
                                         unsigned b0, unsigned b1) {
    asm volatile(
        "mma.sync.aligned.m16n8k8.row.col.f32.tf32.tf32.f32 "
        "{%0,%1,%2,%3}, {%4,%5,%6,%7}, {%8,%9}, {%0,%1,%2,%3};"
        : "+f"(d[0]), "+f"(d[1]), "+f"(d[2]), "+f"(d[3])
        : "r"(a[0]), "r"(a[1]), "r"(a[2]), "r"(a[3]), "r"(b0), "r"(b1));
}

__device__ __forceinline__ int rt_off(int n, int c) {
    return (n >> 6) * 1024 + ((n & 63) >> 3) * 128 +
           (((c & 7) << 2) + (n & 3)) * 4 + ((n >> 2) & 1) + 2 * (c >> 3);
}

// ---------------------------------------------------------------------------
// Kernel 1: Conv1d (NCH, OIH, SAME pad=2) + bias -> g_rt (tf32-rounded,
// fragment-ordered). grid (16, 8) = 128 blocks, block 128.
// ---------------------------------------------------------------------------
__global__ void conv_kernel(const float* __restrict__ r,
                            const float* __restrict__ w,
                            const float* __restrict__ bias) {
    __shared__ float sr[Cc][CNTILE + 4];
    __shared__ float sws[Cc * KW * Cc];   // [ci][k][c_out]
    __shared__ float sb[Cc];

    const int b  = blockIdx.y;
    const int n0 = blockIdx.x * CNTILE;
    const int t  = threadIdx.x;

    for (int i = t; i < Cc * (CNTILE + 4); i += CTHREADS) {
        int ci = i / (CNTILE + 4);
        int j  = i % (CNTILE + 4);
        int n  = n0 + j - 2;
        sr[ci][j] = (n >= 0 && n < NIN) ? r[((size_t)b * Cc + ci) * NIN + n] : 0.0f;
    }
    for (int i = t; i < Cc * Cc * KW; i += CTHREADS) {
        int c  = i / (Cc * KW);
        int rm = i % (Cc * KW);
        int ci = rm / KW;
        int k  = rm % KW;
        sws[(ci * KW + k) * Cc + c] = w[i];
    }
    if (t < Cc) sb[t] = bias[t];
    __syncthreads();

    const int nl = t & (CNTILE - 1);
    const int cg = t >> 5;            // 0..3, channels cg*4..cg*4+3
    const int n  = n0 + nl;

    float a[4];
    #pragma unroll
    for (int q = 0; q < 4; q++) a[q] = sb[cg * 4 + q];

    #pragma unroll
    for (int k = 0; k < KW; k++) {
        #pragma unroll
        for (int ci = 0; ci < Cc; ci++) {
            float v = sr[ci][nl + k];
            float4 wv = *reinterpret_cast<const float4*>(&sws[(ci * KW + k) * Cc + cg * 4]);
            a[0] += v * wv.x; a[1] += v * wv.y; a[2] += v * wv.z; a[3] += v * wv.w;
        }
    }

    float* dst = g_rt + (size_t)b * NIN * Cc;
    #pragma unroll
    for (int q = 0; q < 4; q++) {
        int c = cg * 4 + q;
        dst[rt_off(n, c)] = __uint_as_float(f2tf32(a[q]));
    }
}

// ---------------------------------------------------------------------------
// Kernel 2: Gaussian transform as tf32 MMA + k-reduce + linear C->OUT_C.
// grid (MT, B) = (16, 8) = 128 blocks, block 1024 (32 warps).
// Warp w: msub = w&3 (16 m rows), kq = w>>2 (64 n).
// ALL B fragments preloaded into registers (8 coalesced LDG.128 per thread);
// xn delivered via register shuffle. Hot loop has ZERO memory operations.
// ---------------------------------------------------------------------------
__global__ void __launch_bounds__(GTHREADS, 1)
gauss_mma_kernel(const float* __restrict__ xc,
                 const float* __restrict__ xt,
                 const float* __restrict__ sigma,
                 const float* __restrict__ lw,
                 const float* __restrict__ lb,
                 float* __restrict__ out) {
    __shared__ __align__(16) float zred[KQ][MTILE][Cc];   // 32 KB partials
    __shared__ float shlw[OUTC * Cc];                     // 2 KB
    __shared__ float sh_nh[Cc];
    __shared__ int   sh_alleq;

    const int b  = blockIdx.y;
    const int mt = blockIdx.x;
    const int t  = threadIdx.x;
    const int l  = t & 31;
    const int w  = t >> 5;
    const int msub = w & 3;
    const int kq   = w >> 2;

    if (t < Cc) {
        float sg = sigma[t];
        sh_nh[t] = -0.5f * expf(-2.0f * sg) * LOG2E;
    }
    if (t == 0) {
        float s0 = sigma[0];
        int eq = 1;
        #pragma unroll
        for (int c = 1; c < Cc; c++) eq &= (sigma[c] == s0);
        sh_alleq = eq;
    }
    for (int i = t; i < OUTC * Cc; i += GTHREADS) shlw[i] = lw[i];
    __syncthreads();

    if (sh_alleq) {
        // ---- tf32 MMA fast path: register-resident hot loop ----
        const float nh = sh_nh[0];
        const int mrow = mt * MTILE + msub * 16 + (l >> 2);
        const float xm0 = __ldg(xt + (size_t)b * NOUT + mrow);
        const float xm1 = __ldg(xt + (size_t)b * NOUT + mrow + 8);

        // preload B fragments: 8 coalesced LDG.128 (warp reads 512B runs)
        const float4* Bg = reinterpret_cast<const float4*>(
            g_rt + (size_t)b * NIN * Cc + kq * 1024);
        float4 Bf[KSTEPS];
        #pragma unroll
        for (int ks = 0; ks < KSTEPS; ks++) Bf[ks] = __ldg(&Bg[ks * 32 + l]);

        // preload x-context for this warp's 64 n (coalesced)
        const float* xcb = xc + (size_t)b * NIN + kq * 64;
        float xa = __ldg(xcb + l);
        float xb = __ldg(xcb + 32 + l);

        float D0[4] = {0.f, 0.f, 0.f, 0.f};
        float D1[4] = {0.f, 0.f, 0.f, 0.f};

        #pragma unroll
        for (int ks = 0; ks < KSTEPS; ks++) {
            const float xsrc = (ks < 4) ? xa : xb;
            const int srca = (ks & 3) * 8 + (l & 3);
            float xna = __shfl_sync(0xffffffffu, xsrc, srca);
            float xnb = __shfl_sync(0xffffffffu, xsrc, srca + 4);
            unsigned A[4];
            float d;
            // ex2 bits used directly as tf32 (HW truncates) — no CVT in chain
            d = xm0 - xna; A[0] = __float_as_uint(ex2a(d * d * nh));
            d = xm1 - xna; A[1] = __float_as_uint(ex2a(d * d * nh));
            d = xm0 - xnb; A[2] = __float_as_uint(ex2a(d * d * nh));
            d = xm1 - xnb; A[3] = __float_as_uint(ex2a(d * d * nh));
            mma_tf32(D0, A, __float_as_uint(Bf[ks].x), __float_as_uint(Bf[ks].y));
            mma_tf32(D1, A, __float_as_uint(Bf[ks].z), __float_as_uint(Bf[ks].w));
        }

        const int ml = msub * 16 + (l >> 2);
        const int c0 = (l & 3) * 2;
        *reinterpret_cast<float2*>(&zred[kq][ml][c0])         = make_float2(D0[0], D0[1]);
        *reinterpret_cast<float2*>(&zred[kq][ml + 8][c0])     = make_float2(D0[2], D0[3]);
        *reinterpret_cast<float2*>(&zred[kq][ml][c0 + 8])     = make_float2(D1[0], D1[1]);
        *reinterpret_cast<float2*>(&zred[kq][ml + 8][c0 + 8]) = make_float2(D1[2], D1[3]);
    } else {
        // ---- generic per-channel sigma fallback (correct, not fast) ----
        float nhc[8];
        const int chalf = l & 1;
        #pragma unroll
        for (int j = 0; j < 8; j++) nhc[j] = sh_nh[chalf * 8 + j];
        const int mloc = msub * 16 + (l >> 1);
        const float xm = __ldg(xt + (size_t)b * NOUT + mt * MTILE + mloc);
        const float* rtb = g_rt + (size_t)b * NIN * Cc;
        float acc[8];
        #pragma unroll
        for (int j = 0; j < 8; j++) acc[j] = 0.0f;
        for (int i = 0; i < NIN / KQ; i++) {
            const int n = kq * (NIN / KQ) + i;
            float dx = xm - __ldg(xc + (size_t)b * NIN + n);
            float d  = dx * dx;
            #pragma unroll
            for (int j = 0; j < 8; j++) {
                int c = chalf * 8 + j;
                acc[j] += ex2a(d * nhc[j]) * __ldg(rtb + rt_off(n, c));
            }
        }
        float* zp = &zred[kq][mloc][chalf * 8];
        *reinterpret_cast<float4*>(zp)     = make_float4(acc[0], acc[1], acc[2], acc[3]);
        *reinterpret_cast<float4*>(zp + 4) = make_float4(acc[4], acc[5], acc[6], acc[7]);
    }
    __syncthreads();

    // linear C -> OUT_C + bias: thread t -> (ml = t>>4, 2 outputs at og=(t&15)*2)
    {
        const int ml = t >> 4;            // 0..63
        const int og = (t & 15) * 2;      // 0..30
        float z[Cc];
        #pragma unroll
        for (int c = 0; c < Cc; c += 4) {
            float4 s0 = *reinterpret_cast<const float4*>(&zred[0][ml][c]);
            #pragma unroll
            for (int q = 1; q < KQ; q++) {
                float4 p = *reinterpret_cast<const float4*>(&zred[q][ml][c]);
                s0.x += p.x; s0.y += p.y; s0.z += p.z; s0.w += p.w;
            }
            z[c] = s0.x; z[c + 1] = s0.y; z[c + 2] = s0.z; z[c + 3] = s0.w;
        }
        float o0 = __ldg(lb + og);
        float o1 = __ldg(lb + og + 1);
        #pragma unroll
        for (int c = 0; c < Cc; c++) {
            float zc = z[c];
            o0 += zc * shlw[(og + 0) * Cc + c];
            o1 += zc * shlw[(og + 1) * Cc + c];
        }
        *reinterpret_cast<float2*>(
            out + (((size_t)b * NOUT) + mt * MTILE + ml) * OUTC + og) =
            make_float2(o0, o1);
    }
}

// ---------------------------------------------------------------------------
// Launch. Inputs (metadata order):
// 0 r (8,16,512) | 1 x_context (8,512,1) | 2 y_context (unused) |
// 3 x_target (8,1024,1) | 4 conv_w (16,16,5) | 5 conv_b (16) |
// 6 sigma (16) | 7 lin_w (32,16) | 8 lin_b (32)  -> out (8,1024,32) f32
// ---------------------------------------------------------------------------
extern "C" void kernel_launch(void* const* d_in, const int* in_sizes, int n_in,
                              void* d_out, int out_size) {
    const float* r      = (const float*)d_in[0];
    const float* xc     = (const float*)d_in[1];
    const float* xt     = (const float*)d_in[3];
    const float* conv_w = (const float*)d_in[4];
    const float* conv_b = (const float*)d_in[5];
    const float* sigma  = (const float*)d_in[6];
    const float* lin_w  = (const float*)d_in[7];
    const float* lin_b  = (const float*)d_in[8];
    float* out = (float*)d_out;

    conv_kernel<<<dim3(NIN / CNTILE, Bq), CTHREADS>>>(r, conv_w, conv_b);
    gauss_mma_kernel<<<dim3(MT, Bq), GTHREADS>>>(xc, xt, sigma, lin_w, lin_b, out);
}

// round 11
// speedup vs baseline: 1.4010x; 1.3308x over previous
#include <cuda_runtime.h>
#include <cstdint>

// Problem constants
#define Bq     8
#define NIN    512
#define NOUT   1024
#define Cc     16
#define OUTC   32
#define KW     5

// Conv tiling
#define CNTILE 32
#define CTHREADS 128

// Gauss-MMA tiling
#define MTILE  64                 // m per block
#define MT     (NOUT / MTILE)     // 16
#define GTHREADS 512              // 16 warps: 4 m-subtiles x 4 k-quarters
#define KQ     4
#define KSTEPS 16                 // (NIN/KQ)/8

#define LOG2E 1.4426950408889634f

// conv output, stored in PER-THREAD FRAGMENT ORDER for the gauss MMA:
// off(n,c) = (n>>6)*1024 + ((n&63)>>3)*128 + ((c&7)*4+(n&3))*4
//            + ((n>>2)&1) + 2*(c>>3)
__device__ float g_rt[Bq * NIN * Cc];

__device__ __forceinline__ float ex2a(float x) {
    float r; asm("ex2.approx.f32 %0, %1;" : "=f"(r) : "f"(x)); return r;
}
__device__ __forceinline__ unsigned f2tf32(float x) {
    unsigned r; asm("cvt.rna.tf32.f32 %0, %1;" : "=r"(r) : "f"(x)); return r;
}
__device__ __forceinline__ void mma_tf32(float d[4], const unsigned a[4],
                                         unsigned b0, unsigned b1) {
    asm volatile(
        "mma.sync.aligned.m16n8k8.row.col.f32.tf32.tf32.f32 "
        "{%0,%1,%2,%3}, {%4,%5,%6,%7}, {%8,%9}, {%0,%1,%2,%3};"
        : "+f"(d[0]), "+f"(d[1]), "+f"(d[2]), "+f"(d[3])
        : "r"(a[0]), "r"(a[1]), "r"(a[2]), "r"(a[3]), "r"(b0), "r"(b1));
}

__device__ __forceinline__ int rt_off(int n, int c) {
    return (n >> 6) * 1024 + ((n & 63) >> 3) * 128 +
           (((c & 7) << 2) + (n & 3)) * 4 + ((n >> 2) & 1) + 2 * (c >> 3);
}

// ---------------------------------------------------------------------------
// Kernel 1: Conv1d (NCH, OIH, SAME pad=2) + bias -> g_rt (tf32-rounded,
// fragment-ordered). grid (16, 8) = 128 blocks, block 128.
// ---------------------------------------------------------------------------
__global__ void conv_kernel(const float* __restrict__ r,
                            const float* __restrict__ w,
                            const float* __restrict__ bias) {
    __shared__ float sr[Cc][CNTILE + 4];
    __shared__ float sws[Cc * KW * Cc];   // [ci][k][c_out]
    __shared__ float sb[Cc];

    const int b  = blockIdx.y;
    const int n0 = blockIdx.x * CNTILE;
    const int t  = threadIdx.x;

    for (int i = t; i < Cc * (CNTILE + 4); i += CTHREADS) {
        int ci = i / (CNTILE + 4);
        int j  = i % (CNTILE + 4);
        int n  = n0 + j - 2;
        sr[ci][j] = (n >= 0 && n < NIN) ? r[((size_t)b * Cc + ci) * NIN + n] : 0.0f;
    }
    for (int i = t; i < Cc * Cc * KW; i += CTHREADS) {
        int c  = i / (Cc * KW);
        int rm = i % (Cc * KW);
        int ci = rm / KW;
        int k  = rm % KW;
        sws[(ci * KW + k) * Cc + c] = w[i];
    }
    if (t < Cc) sb[t] = bias[t];
    __syncthreads();

    const int nl = t & (CNTILE - 1);
    const int cg = t >> 5;            // 0..3, channels cg*4..cg*4+3
    const int n  = n0 + nl;

    float a[4];
    #pragma unroll
    for (int q = 0; q < 4; q++) a[q] = sb[cg * 4 + q];

    #pragma unroll
    for (int k = 0; k < KW; k++) {
        #pragma unroll
        for (int ci = 0; ci < Cc; ci++) {
            float v = sr[ci][nl + k];
            float4 wv = *reinterpret_cast<const float4*>(&sws[(ci * KW + k) * Cc + cg * 4]);
            a[0] += v * wv.x; a[1] += v * wv.y; a[2] += v * wv.z; a[3] += v * wv.w;
        }
    }

    float* dst = g_rt + (size_t)b * NIN * Cc;
    #pragma unroll
    for (int q = 0; q < 4; q++) {
        int c = cg * 4 + q;
        dst[rt_off(n, c)] = __uint_as_float(f2tf32(a[q]));
    }
}

// ---------------------------------------------------------------------------
// Kernel 2: Gaussian transform as tf32 MMA + 2-stage reduce + linear.
// grid (MT, B) = (16, 8) = 128 blocks, block 512 (16 warps).
// Warp w: msub = w&3 (16 m rows), kq = w>>2 (128 n, 16 ksteps).
// B fragments preloaded into registers (16 coalesced LDG.128/thread);
// xn via register shuffle. Hot loop has zero memory operations.
// Light epilogue: 4->1 set fold (256 threads), then linear with transposed
// weights (one 128B row wavefront per channel).
// ---------------------------------------------------------------------------
__global__ void __launch_bounds__(GTHREADS, 1)
gauss_mma_kernel(const float* __restrict__ xc,
                 const float* __restrict__ xt,
                 const float* __restrict__ sigma,
                 const float* __restrict__ lw,
                 const float* __restrict__ lb,
                 float* __restrict__ out) {
    __shared__ __align__(16) float zred[KQ][MTILE][Cc];   // 16 KB partials
    __shared__ __align__(16) float shlwT[Cc * OUTC];      // 2 KB transposed [c][o]
    __shared__ float sh_nh[Cc];
    __shared__ int   sh_alleq;

    const int b  = blockIdx.y;
    const int mt = blockIdx.x;
    const int t  = threadIdx.x;
    const int l  = t & 31;
    const int w  = t >> 5;
    const int msub = w & 3;
    const int kq   = w >> 2;

    if (t < Cc) {
        float sg = sigma[t];
        sh_nh[t] = -0.5f * expf(-2.0f * sg) * LOG2E;
    }
    if (t == 0) {
        float s0 = sigma[0];
        int eq = 1;
        #pragma unroll
        for (int c = 1; c < Cc; c++) eq &= (sigma[c] == s0);
        sh_alleq = eq;
    }
    // transposed linear weights: shlwT[c*OUTC + o] = lw[o*Cc + c]
    if (t < Cc * OUTC) {
        int c = t >> 5, o = t & 31;
        shlwT[t] = lw[o * Cc + c];
    }
    __syncthreads();

    if (sh_alleq) {
        // ---- tf32 MMA fast path: register-resident hot loop ----
        const float nh = sh_nh[0];
        const int mrow = mt * MTILE + msub * 16 + (l >> 2);
        const float xm0 = __ldg(xt + (size_t)b * NOUT + mrow);
        const float xm1 = __ldg(xt + (size_t)b * NOUT + mrow + 8);

        // preload B fragments: 16 coalesced LDG.128 per thread
        const float4* Bg = reinterpret_cast<const float4*>(
            g_rt + (size_t)b * NIN * Cc + kq * 2048);
        float4 Bf[KSTEPS];
        #pragma unroll
        for (int ks = 0; ks < KSTEPS; ks++)
            Bf[ks] = __ldg(&Bg[(ks >> 3) * 256 + (ks & 7) * 32 + l]);

        // preload x-context for this warp's 128 n (coalesced, 4 regs)
        const float* xcb = xc + (size_t)b * NIN + kq * 128;
        float xr0 = __ldg(xcb + l);
        float xr1 = __ldg(xcb + 32 + l);
        float xr2 = __ldg(xcb + 64 + l);
        float xr3 = __ldg(xcb + 96 + l);

        float D0[4] = {0.f, 0.f, 0.f, 0.f};
        float D1[4] = {0.f, 0.f, 0.f, 0.f};

        #pragma unroll
        for (int ks = 0; ks < KSTEPS; ks++) {
            const float xsrc = (ks < 8) ? ((ks < 4) ? xr0 : xr1)
                                        : ((ks < 12) ? xr2 : xr3);
            const int srca = (ks & 3) * 8 + (l & 3);
            float xna = __shfl_sync(0xffffffffu, xsrc, srca);
            float xnb = __shfl_sync(0xffffffffu, xsrc, srca + 4);
            unsigned A[4];
            float d;
            // ex2 bits used directly as tf32 (HW truncates) — no CVT in chain
            d = xm0 - xna; A[0] = __float_as_uint(ex2a(d * d * nh));
            d = xm1 - xna; A[1] = __float_as_uint(ex2a(d * d * nh));
            d = xm0 - xnb; A[2] = __float_as_uint(ex2a(d * d * nh));
            d = xm1 - xnb; A[3] = __float_as_uint(ex2a(d * d * nh));
            mma_tf32(D0, A, __float_as_uint(Bf[ks].x), __float_as_uint(Bf[ks].y));
            mma_tf32(D1, A, __float_as_uint(Bf[ks].z), __float_as_uint(Bf[ks].w));
        }

        const int ml = msub * 16 + (l >> 2);
        const int c0 = (l & 3) * 2;
        *reinterpret_cast<float2*>(&zred[kq][ml][c0])         = make_float2(D0[0], D0[1]);
        *reinterpret_cast<float2*>(&zred[kq][ml + 8][c0])     = make_float2(D0[2], D0[3]);
        *reinterpret_cast<float2*>(&zred[kq][ml][c0 + 8])     = make_float2(D1[0], D1[1]);
        *reinterpret_cast<float2*>(&zred[kq][ml + 8][c0 + 8]) = make_float2(D1[2], D1[3]);
    } else {
        // ---- generic per-channel sigma fallback (correct, not fast) ----
        float nhc[8];
        const int chalf = l & 1;
        #pragma unroll
        for (int j = 0; j < 8; j++) nhc[j] = sh_nh[chalf * 8 + j];
        const int mloc = msub * 16 + (l >> 1);
        const float xm = __ldg(xt + (size_t)b * NOUT + mt * MTILE + mloc);
        const float* rtb = g_rt + (size_t)b * NIN * Cc;
        float acc[8];
        #pragma unroll
        for (int j = 0; j < 8; j++) acc[j] = 0.0f;
        for (int i = 0; i < NIN / KQ; i++) {
            const int n = kq * (NIN / KQ) + i;
            float dx = xm - __ldg(xc + (size_t)b * NIN + n);
            float d  = dx * dx;
            #pragma unroll
            for (int j = 0; j < 8; j++) {
                int c = chalf * 8 + j;
                acc[j] += ex2a(d * nhc[j]) * __ldg(rtb + rt_off(n, c));
            }
        }
        float* zp = &zred[kq][mloc][chalf * 8];
        *reinterpret_cast<float4*>(zp)     = make_float4(acc[0], acc[1], acc[2], acc[3]);
        *reinterpret_cast<float4*>(zp + 4) = make_float4(acc[4], acc[5], acc[6], acc[7]);
    }
    __syncthreads();

    // Stage A: fold 4 partial sets into set 0 (256 threads, 1 float4 each)
    {
        float4* rv = reinterpret_cast<float4*>(zred);
        const int NV = MTILE * Cc / 4;   // 256 slots per set
        if (t < NV) {
            float4 s = rv[t];
            #pragma unroll
            for (int q = 1; q < KQ; q++) {
                float4 p = rv[q * NV + t];
                s.x += p.x; s.y += p.y; s.z += p.z; s.w += p.w;
            }
            rv[t] = s;
        }
    }
    __syncthreads();

    // linear C -> OUT_C + bias: thread t -> (ml = t>>3, 4 outputs at og=(t&7)*4)
    {
        const int ml = t >> 3;            // 0..63
        const int og = (t & 7) * 4;       // 0..28
        float z[Cc];
        #pragma unroll
        for (int c = 0; c < Cc; c += 4) {
            float4 zv = *reinterpret_cast<const float4*>(&zred[0][ml][c]);
            z[c] = zv.x; z[c + 1] = zv.y; z[c + 2] = zv.z; z[c + 3] = zv.w;
        }
        float4 o4;
        o4.x = __ldg(lb + og + 0); o4.y = __ldg(lb + og + 1);
        o4.z = __ldg(lb + og + 2); o4.w = __ldg(lb + og + 3);
        #pragma unroll
        for (int c = 0; c < Cc; c++) {
            float zc = z[c];
            float4 wv = *reinterpret_cast<const float4*>(&shlwT[c * OUTC + og]);
            o4.x += zc * wv.x; o4.y += zc * wv.y;
            o4.z += zc * wv.z; o4.w += zc * wv.w;
        }
        *reinterpret_cast<float4*>(
            out + (((size_t)b * NOUT) + mt * MTILE + ml) * OUTC + og) = o4;
    }
}

// ---------------------------------------------------------------------------
// Launch. Inputs (metadata order):
// 0 r (8,16,512) | 1 x_context (8,512,1) | 2 y_context (unused) |
// 3 x_target (8,1024,1) | 4 conv_w (16,16,5) | 5 conv_b (16) |
// 6 sigma (16) | 7 lin_w (32,16) | 8 lin_b (32)  -> out (8,1024,32) f32
// ---------------------------------------------------------------------------
extern "C" void kernel_launch(void* const* d_in, const int* in_sizes, int n_in,
                              void* d_out, int out_size) {
    const float* r      = (const float*)d_in[0];
    const float* xc     = (const float*)d_in[1];
    const float* xt     = (const float*)d_in[3];
    const float* conv_w = (const float*)d_in[4];
    const float* conv_b = (const float*)d_in[5];
    const float* sigma  = (const float*)d_in[6];
    const float* lin_w  = (const float*)d_in[7];
    const float* lin_b  = (const float*)d_in[8];
    float* out = (float*)d_out;

    conv_kernel<<<dim3(NIN / CNTILE, Bq), CTHREADS>>>(r, conv_w, conv_b);
    gauss_mma_kernel<<<dim3(MT, Bq), GTHREADS>>>(xc, xt, sigma, lin_w, lin_b, out);
}